// round 4
// baseline (speedup 1.0000x reference)
#include <cuda_runtime.h>
#include <cuda_bf16.h>
#include <cstdint>

// CartesianToDihedral: (1024, 2048, 3, 3) f32 -> (angles (1024,12282), first_three (1024,9))
// W=8 windows/thread, aligned float4 loads, third cross eliminated via
// (n1 x u).n2 == -e0.n2 (u normalized), no shared memory.

namespace {
constexpr int B_SZ        = 1024;
constexpr int PTS_PER_ROW = 6144;                 // 2048*3
constexpr int FLT_PER_ROW = PTS_PER_ROW * 3;      // 18432
constexpr int NWIN        = PTS_PER_ROW - 3;      // 6141
constexpr int OUT_STRIDE  = 2 * NWIN;             // 12282
constexpr int W           = 8;                    // windows per thread
constexpr int TPB         = 256;
constexpr int WIN_PER_BLK = W * TPB;              // 2048
constexpr int CHUNKS      = 3;                    // 3*2048 = 6144 >= 6141
constexpr long long TOTAL_IN = (long long)B_SZ * FLT_PER_ROW;  // 18,874,368
}

__device__ __forceinline__ void dihedral_core(
    const float* e0, const float* e1, const float* e2,
    float& sv, float& cv)
{
    // u = normalize(e1 + 1e-8)
    const float ux0 = e1[0] + 1e-8f;
    const float uy0 = e1[1] + 1e-8f;
    const float uz0 = e1[2] + 1e-8f;
    const float rin = rsqrtf(fmaf(ux0, ux0, fmaf(uy0, uy0, uz0 * uz0)));
    const float ux = ux0 * rin, uy = uy0 * rin, uz = uz0 * rin;

    // n1 = cross(e0, u)
    const float n1x = fmaf(e0[1], uz, -e0[2] * uy);
    const float n1y = fmaf(e0[2], ux, -e0[0] * uz);
    const float n1z = fmaf(e0[0], uy, -e0[1] * ux);
    // n2 = cross(u, e2)
    const float n2x = fmaf(uy, e2[2], -uz * e2[1]);
    const float n2y = fmaf(uz, e2[0], -ux * e2[2]);
    const float n2z = fmaf(ux, e2[1], -uy * e2[0]);

    // xc = n1.n2 + 1e-8 ;  yc = (cross(n1,u)).n2 == -e0.n2   (since u.n2 == 0, |u|=1)
    const float xc = fmaf(n1x, n2x, fmaf(n1y, n2y, fmaf(n1z, n2z, 1e-8f)));
    const float yc = -fmaf(e0[0], n2x, fmaf(e0[1], n2y, e0[2] * n2z));

    const float r2 = fmaf(xc, xc, yc * yc);
    const float ri = rsqrtf(r2);
    sv = (r2 > 0.0f) ? yc * ri : 0.0f;   // atan2(0,0)=0
    cv = (r2 > 0.0f) ? xc * ri : 1.0f;
}

__global__ __launch_bounds__(TPB)
void dihedral_kernel(const float* __restrict__ in, float* __restrict__ out) {
    const int bid   = blockIdx.x;
    const int batch = bid / CHUNKS;
    const int chunk = bid - batch * CHUNKS;
    const int gw0   = chunk * WIN_PER_BLK + threadIdx.x * W;  // multiple of 8

    const long long rowBase = (long long)batch * FLT_PER_ROW;
    const long long fbase   = rowBase + (long long)gw0 * 3;   // multiple of 4 (gw0*3 % 4 == 0)

    // Load 11 points = 33 floats (36 with pad) as 9 aligned float4s.
    float f[36];
    if (fbase + 36 <= TOTAL_IN) {                  // all but the last thread of the grid
        const float4* p4 = reinterpret_cast<const float4*>(in + fbase);
        #pragma unroll
        for (int t = 0; t < 9; t++) {
            const float4 v = p4[t];
            f[4*t+0] = v.x; f[4*t+1] = v.y; f[4*t+2] = v.z; f[4*t+3] = v.w;
        }
    } else {
        #pragma unroll
        for (int t = 0; t < 36; t++)
            f[t] = (fbase + t < TOTAL_IN) ? in[fbase + t] : 0.0f;
    }

    // Edges e_j = p_j - p_{j+1}, j = 0..9
    float e[W + 2][3];
    #pragma unroll
    for (int j = 0; j < W + 2; j++) {
        e[j][0] = f[3*j+0] - f[3*j+3];
        e[j][1] = f[3*j+1] - f[3*j+4];
        e[j][2] = f[3*j+2] - f[3*j+5];
    }

    float sv[W], cv[W];
    #pragma unroll
    for (int w = 0; w < W; w++)
        dihedral_core(e[w], e[w+1], e[w+2], sv[w], cv[w]);

    const long long ob = (long long)batch * OUT_STRIDE;

    if (gw0 + W <= NWIN) {
        // sin: (ob+gw0) is even -> 8B-aligned float2 stores
        float2* s2 = reinterpret_cast<float2*>(out + ob + gw0);
        #pragma unroll
        for (int t = 0; t < W/2; t++)
            s2[t] = make_float2(sv[2*t], sv[2*t+1]);
        // cos: offset NWIN (odd) -> scalar stores (warp-contiguous)
        float* cp = out + ob + NWIN + gw0;
        #pragma unroll
        for (int t = 0; t < W; t++)
            cp[t] = cv[t];
    } else {
        #pragma unroll
        for (int w = 0; w < W; w++) {
            if (gw0 + w < NWIN) {
                out[ob + gw0 + w]        = sv[w];
                out[ob + NWIN + gw0 + w] = cv[w];
            }
        }
    }

    // first_three: 9 floats per batch appended after all angle rows.
    if (chunk == 0 && threadIdx.x < 9) {
        out[(long long)B_SZ * OUT_STRIDE + (long long)batch * 9 + threadIdx.x] =
            in[rowBase + threadIdx.x];
    }
}

extern "C" void kernel_launch(void* const* d_in, const int* in_sizes, int n_in,
                              void* d_out, int out_size) {
    const float* in = (const float*)d_in[0];
    float* out = (float*)d_out;
    dihedral_kernel<<<B_SZ * CHUNKS, TPB>>>(in, out);
}

// round 5
// speedup vs baseline: 1.7105x; 1.7105x over previous
#include <cuda_runtime.h>
#include <cuda_bf16.h>
#include <cstdint>

// CartesianToDihedral: (1024, 2048, 3, 3) f32 -> (angles (1024,12282), first_three (1024,9))
// W=4 windows/thread (R2 register shape, 32 regs), aligned float4 loads,
// third cross eliminated: yc = (n1 x u).n2 == -e0.n2 since u.n2==0, |u|=1.

namespace {
constexpr int B_SZ        = 1024;
constexpr int PTS_PER_ROW = 6144;                 // 2048*3
constexpr int FLT_PER_ROW = PTS_PER_ROW * 3;      // 18432
constexpr int NWIN        = PTS_PER_ROW - 3;      // 6141
constexpr int OUT_STRIDE  = 2 * NWIN;             // 12282
constexpr int W           = 4;                    // windows per thread
constexpr int TPB         = 256;
constexpr int WIN_PER_BLK = W * TPB;              // 1024
constexpr int CHUNKS      = 6;                    // 6*1024 = 6144 >= 6141
constexpr long long TOTAL_IN = (long long)B_SZ * FLT_PER_ROW;  // 18,874,368
}

__device__ __forceinline__ void dihedral_core(
    const float* e0, const float* e1, const float* e2,
    float& sv, float& cv)
{
    // u = normalize(e1 + 1e-8)
    const float ux0 = e1[0] + 1e-8f;
    const float uy0 = e1[1] + 1e-8f;
    const float uz0 = e1[2] + 1e-8f;
    const float rin = rsqrtf(fmaf(ux0, ux0, fmaf(uy0, uy0, uz0 * uz0)));
    const float ux = ux0 * rin, uy = uy0 * rin, uz = uz0 * rin;

    // n1 = cross(e0, u)
    const float n1x = fmaf(e0[1], uz, -e0[2] * uy);
    const float n1y = fmaf(e0[2], ux, -e0[0] * uz);
    const float n1z = fmaf(e0[0], uy, -e0[1] * ux);
    // n2 = cross(u, e2)
    const float n2x = fmaf(uy, e2[2], -uz * e2[1]);
    const float n2y = fmaf(uz, e2[0], -ux * e2[2]);
    const float n2z = fmaf(ux, e2[1], -uy * e2[0]);

    // xc = n1.n2 + 1e-8 ; yc = (n1 x u).n2 == -e0.n2
    const float xc = fmaf(n1x, n2x, fmaf(n1y, n2y, fmaf(n1z, n2z, 1e-8f)));
    const float yc = -fmaf(e0[0], n2x, fmaf(e0[1], n2y, e0[2] * n2z));

    const float r2 = fmaf(xc, xc, yc * yc);
    const float ri = rsqrtf(r2);
    sv = (r2 > 0.0f) ? yc * ri : 0.0f;   // atan2(0,0)=0
    cv = (r2 > 0.0f) ? xc * ri : 1.0f;
}

__global__ __launch_bounds__(TPB)
void dihedral_kernel(const float* __restrict__ in, float* __restrict__ out) {
    const int bid   = blockIdx.x;
    const int batch = bid / CHUNKS;
    const int chunk = bid - batch * CHUNKS;
    const int gw0   = chunk * WIN_PER_BLK + threadIdx.x * W;

    const long long rowBase = (long long)batch * FLT_PER_ROW;
    const long long fbase   = rowBase + (long long)gw0 * 3;   // multiple of 4

    // Load 7 points = 21 floats (24 with pad) as 6 aligned float4s.
    float f[24];
    if (fbase + 24 <= TOTAL_IN) {                 // all but the final tail thread
        const float4* p4 = reinterpret_cast<const float4*>(in + fbase);
        #pragma unroll
        for (int t = 0; t < 6; t++) {
            const float4 v = p4[t];
            f[4*t+0] = v.x; f[4*t+1] = v.y; f[4*t+2] = v.z; f[4*t+3] = v.w;
        }
    } else {
        #pragma unroll
        for (int t = 0; t < 24; t++)
            f[t] = (fbase + t < TOTAL_IN) ? in[fbase + t] : 0.0f;
    }

    // Edges e_j = p_j - p_{j+1}, j = 0..5
    float e[W + 2][3];
    #pragma unroll
    for (int j = 0; j < W + 2; j++) {
        e[j][0] = f[3*j+0] - f[3*j+3];
        e[j][1] = f[3*j+1] - f[3*j+4];
        e[j][2] = f[3*j+2] - f[3*j+5];
    }

    float sv[W], cv[W];
    #pragma unroll
    for (int w = 0; w < W; w++)
        dihedral_core(e[w], e[w+1], e[w+2], sv[w], cv[w]);

    const long long ob = (long long)batch * OUT_STRIDE;

    if (gw0 + W <= NWIN) {
        // sin: (ob+gw0) even -> 8B-aligned float2 stores
        float2* s2 = reinterpret_cast<float2*>(out + ob + gw0);
        s2[0] = make_float2(sv[0], sv[1]);
        s2[1] = make_float2(sv[2], sv[3]);
        // cos: offset NWIN (odd) -> scalar stores (warp-contiguous)
        float* cp = out + ob + NWIN + gw0;
        cp[0] = cv[0]; cp[1] = cv[1]; cp[2] = cv[2]; cp[3] = cv[3];
    } else {
        #pragma unroll
        for (int w = 0; w < W; w++) {
            if (gw0 + w < NWIN) {
                out[ob + gw0 + w]        = sv[w];
                out[ob + NWIN + gw0 + w] = cv[w];
            }
        }
    }

    // first_three: 9 floats per batch appended after all angle rows.
    if (chunk == 0 && threadIdx.x < 9) {
        out[(long long)B_SZ * OUT_STRIDE + (long long)batch * 9 + threadIdx.x] =
            in[rowBase + threadIdx.x];
    }
}

extern "C" void kernel_launch(void* const* d_in, const int* in_sizes, int n_in,
                              void* d_out, int out_size) {
    const float* in = (const float*)d_in[0];
    float* out = (float*)d_out;
    dihedral_kernel<<<B_SZ * CHUNKS, TPB>>>(in, out);
}